// round 4
// baseline (speedup 1.0000x reference)
#include <cuda_runtime.h>
#include <math.h>

#define NB 4
#define NS 512
#define NDIM 512
#define NH 8
#define NDH 64
#define NM (NB*NS)     // 2048

// ---------------- device scratch (no allocations allowed) ----------------
__device__ float g_q[NB*NH*NS*NDH];     // [b][h][s][d]
__device__ float g_k[NB*NH*NS*NDH];
__device__ float g_v[NB*NH*NS*NDH];
__device__ float g_u[NB*NS*NH];         // [b][s][h]
__device__ float g_w[NB*NH*NS];         // [b][h][k] : q-independent positional attn row
__device__ float g_y[NM*NDIM];          // pre-output-projection activations

// =====================================================================
// 3xTF32 tensor-core GEMM (m16n8k8 mma.sync), 128x128 CTA tile, 256 thr.
// A fp32 [M,512] row-major, B fp32 [512,512] row-major (column-offset n0
// pre-applied by caller). hi/lo tf32 split -> error ~2^-22.
// Fragments are pre-permuted into smem so the MMA loop does vector LDS.
// =====================================================================
__device__ __forceinline__ unsigned f2tf(float x) {
    unsigned r;
    asm("cvt.rna.tf32.f32 %0, %1;" : "=r"(r) : "f"(x));
    return r;
}

__device__ __forceinline__ void mma_tf32(float (&d)[4], const unsigned (&a)[4],
                                         unsigned b0, unsigned b1) {
    asm volatile(
        "mma.sync.aligned.m16n8k8.row.col.f32.tf32.tf32.f32 "
        "{%0,%1,%2,%3}, {%4,%5,%6,%7}, {%8,%9}, {%0,%1,%2,%3};"
        : "+f"(d[0]), "+f"(d[1]), "+f"(d[2]), "+f"(d[3])
        : "r"(a[0]), "r"(a[1]), "r"(a[2]), "r"(a[3]), "r"(b0), "r"(b1));
}

// smem: Ah[4096] Al[4096] Bh[4096] Bl[4096] floats = 65536 bytes
#define TF32_SMEM_BYTES 65536

__device__ __forceinline__ void tf32_gemm_core(const float* __restrict__ A,
                                               const float* __restrict__ B,
                                               float* fs, float (&acc)[2][8][4]) {
    float* Ah = fs;
    float* Al = fs + 4096;
    float* Bh = fs + 8192;
    float* Bl = fs + 12288;
    int tid = threadIdx.x;
    int lane = tid & 31, wid = tid >> 5;
    int warp_m = wid >> 1, warp_n = wid & 1;
    int ar = tid >> 1, ac4 = (tid & 1) * 4;   // A: 128 rows, 2 threads/row, 16 k each
    int br = tid >> 3, bc4 = (tid & 7) * 4;   // B: 32 k-rows, 8 threads/row, 16 n each

    for (int k0 = 0; k0 < 512; k0 += 32) {
        // ---- load + split + fragment-scatter A tile (128x32) ----
        int mblk = ar >> 4, mr = ar & 15;
        #pragma unroll
        for (int c = 0; c < 4; c++) {
            int kloc = (ac4 + c) * 4;
            float4 v = *(const float4*)&A[ar * 512 + k0 + kloc];
            float vv[4] = {v.x, v.y, v.z, v.w};
            #pragma unroll
            for (int e = 0; e < 4; e++) {
                int k = kloc + e;
                int kblk = k >> 3, kc = k & 7;
                int reg = ((mr >> 3) & 1) | ((kc >> 2) << 1);
                int lt = (mr & 7) * 4 + (kc & 3);
                int idx = ((kblk * 8 + mblk) * 32 + lt) * 4 + reg;
                float hi = __uint_as_float(f2tf(vv[e]));
                Ah[idx] = hi;
                Al[idx] = __uint_as_float(f2tf(vv[e] - hi));
            }
        }
        // ---- load + split + fragment-scatter B tile (32x128) ----
        {
            int kblk = br >> 3, kc = br & 7;
            int reg = (kc >> 2) & 1, tl = kc & 3;
            #pragma unroll
            for (int c = 0; c < 4; c++) {
                int nloc = (bc4 + c) * 4;
                float4 v = *(const float4*)&B[(k0 + br) * 512 + nloc];
                float vv[4] = {v.x, v.y, v.z, v.w};
                #pragma unroll
                for (int e = 0; e < 4; e++) {
                    int n = nloc + e;
                    int nblk = n >> 3, nc = n & 7;
                    int lt = nc * 4 + tl;
                    int idx = ((kblk * 16 + nblk) * 32 + lt) * 2 + reg;
                    float hi = __uint_as_float(f2tf(vv[e]));
                    Bh[idx] = hi;
                    Bl[idx] = __uint_as_float(f2tf(vv[e] - hi));
                }
            }
        }
        __syncthreads();
        // ---- MMA: 4 k8-blocks, warp covers 32m x 64n ----
        #pragma unroll
        for (int kb = 0; kb < 4; kb++) {
            unsigned ah[2][4], al[2][4];
            #pragma unroll
            for (int mb2 = 0; mb2 < 2; mb2++) {
                int mb = warp_m * 2 + mb2;
                float4 h4 = *(float4*)&Ah[((kb * 8 + mb) * 32 + lane) * 4];
                float4 l4 = *(float4*)&Al[((kb * 8 + mb) * 32 + lane) * 4];
                ah[mb2][0] = __float_as_uint(h4.x); ah[mb2][1] = __float_as_uint(h4.y);
                ah[mb2][2] = __float_as_uint(h4.z); ah[mb2][3] = __float_as_uint(h4.w);
                al[mb2][0] = __float_as_uint(l4.x); al[mb2][1] = __float_as_uint(l4.y);
                al[mb2][2] = __float_as_uint(l4.z); al[mb2][3] = __float_as_uint(l4.w);
            }
            #pragma unroll
            for (int nb = 0; nb < 8; nb++) {
                int nblk = warp_n * 8 + nb;
                float2 h2 = *(float2*)&Bh[((kb * 16 + nblk) * 32 + lane) * 2];
                float2 l2 = *(float2*)&Bl[((kb * 16 + nblk) * 32 + lane) * 2];
                unsigned b0h = __float_as_uint(h2.x), b1h = __float_as_uint(h2.y);
                unsigned b0l = __float_as_uint(l2.x), b1l = __float_as_uint(l2.y);
                #pragma unroll
                for (int mb2 = 0; mb2 < 2; mb2++) {
                    mma_tf32(acc[mb2][nb], ah[mb2], b0h, b1h);
                    mma_tf32(acc[mb2][nb], ah[mb2], b0l, b1l);
                    mma_tf32(acc[mb2][nb], al[mb2], b0h, b1h);
                }
            }
        }
        __syncthreads();
    }
}

// ---------------- QKV projection (tf32) with scatter to [b,h,s,d] ---------
__global__ void __launch_bounds__(256, 2)
qkv_tf32(const float* __restrict__ X, const float* __restrict__ Wq,
         const float* __restrict__ Wk, const float* __restrict__ Wv) {
    extern __shared__ float fs[];
    const float* W = (blockIdx.z == 0) ? Wq : ((blockIdx.z == 1) ? Wk : Wv);
    float* out = (blockIdx.z == 0) ? g_q : ((blockIdx.z == 1) ? g_k : g_v);
    int m0 = blockIdx.y * 128, n0 = blockIdx.x * 128;
    float acc[2][8][4] = {};
    tf32_gemm_core(X + (size_t)m0 * 512, W + n0, fs, acc);

    int lane = threadIdx.x & 31, wid = threadIdx.x >> 5;
    int warp_m = wid >> 1, warp_n = wid & 1;
    int g = lane >> 2, t = lane & 3;
    #pragma unroll
    for (int mb2 = 0; mb2 < 2; mb2++) {
        int mrow = m0 + warp_m * 32 + mb2 * 16 + g;
        #pragma unroll
        for (int nb = 0; nb < 8; nb++) {
            int ncol = n0 + (warp_n * 8 + nb) * 8 + 2 * t;
            int h = ncol >> 6, d = ncol & 63;
            {   // row mrow: c0,c1
                int b = mrow >> 9, s = mrow & 511;
                *(float2*)&out[((b * NH + h) * NS + s) * NDH + d] =
                    make_float2(acc[mb2][nb][0], acc[mb2][nb][1]);
            }
            {   // row mrow+8: c2,c3
                int m2 = mrow + 8;
                int b = m2 >> 9, s = m2 & 511;
                *(float2*)&out[((b * NH + h) * NS + s) * NDH + d] =
                    make_float2(acc[mb2][nb][2], acc[mb2][nb][3]);
            }
        }
    }
}

// ---------------- out = y @ Wo + bo (tf32) ----------------
__global__ void __launch_bounds__(256, 2)
out_tf32(const float* __restrict__ Wo, const float* __restrict__ bo,
         float* __restrict__ out) {
    extern __shared__ float fs[];
    int m0 = blockIdx.y * 128, n0 = blockIdx.x * 128;
    float acc[2][8][4] = {};
    tf32_gemm_core(g_y + (size_t)m0 * 512, Wo + n0, fs, acc);

    int lane = threadIdx.x & 31, wid = threadIdx.x >> 5;
    int warp_m = wid >> 1, warp_n = wid & 1;
    int g = lane >> 2, t = lane & 3;
    #pragma unroll
    for (int mb2 = 0; mb2 < 2; mb2++) {
        int mrow = m0 + warp_m * 32 + mb2 * 16 + g;
        #pragma unroll
        for (int nb = 0; nb < 8; nb++) {
            int ncol = n0 + (warp_n * 8 + nb) * 8 + 2 * t;
            float b0 = bo[ncol], b1 = bo[ncol + 1];
            *(float2*)&out[(size_t)mrow * NDIM + ncol] =
                make_float2(acc[mb2][nb][0] + b0, acc[mb2][nb][1] + b1);
            *(float2*)&out[(size_t)(mrow + 8) * NDIM + ncol] =
                make_float2(acc[mb2][nb][2] + b0, acc[mb2][nb][3] + b1);
        }
    }
}

// ---------------- tiny positional MLP: u[b,s,h] ----------------
__global__ void u_kernel(const float* __restrict__ pos,
                         const float* __restrict__ Wp1, const float* __restrict__ bp1,
                         const float* __restrict__ Wp2, const float* __restrict__ bp2,
                         const float* __restrict__ Wh) {
    int idx = blockIdx.x * blockDim.x + threadIdx.x;
    if (idx >= NM) return;
    const float* pp = pos + idx * 3;
    float p0 = pp[0], p1 = pp[1], p2 = pp[2];
    float h1[3];
    #pragma unroll
    for (int j = 0; j < 3; j++)
        h1[j] = fmaxf(0.0f, p0 * Wp1[j] + p1 * Wp1[3 + j] + p2 * Wp1[6 + j] + bp1[j]);
    float u[NH];
    #pragma unroll
    for (int hh = 0; hh < NH; hh++) u[hh] = 0.0f;
    for (int j = 0; j < 64; j++) {
        float pv = h1[0] * Wp2[j] + h1[1] * Wp2[64 + j] + h1[2] * Wp2[128 + j] + bp2[j];
        #pragma unroll
        for (int hh = 0; hh < NH; hh++) u[hh] += pv * Wh[j * NH + hh];
    }
    #pragma unroll
    for (int hh = 0; hh < NH; hh++) g_u[idx * NH + hh] = u[hh];
}

// w[b,h,k] = softmax_k(-u[b,k,h])
__global__ void pos_w_kernel() {
    __shared__ float red[512];
    int bh = blockIdx.x;
    int b = bh >> 3, h = bh & 7;
    int k = threadIdx.x;
    float t = -g_u[(b * NS + k) * NH + h];
    red[k] = t; __syncthreads();
    for (int s = 256; s > 0; s >>= 1) { if (k < s) red[k] = fmaxf(red[k], red[k + s]); __syncthreads(); }
    float m = red[0]; __syncthreads();
    float e = expf(t - m);
    red[k] = e; __syncthreads();
    for (int s = 256; s > 0; s >>= 1) { if (k < s) red[k] += red[k + s]; __syncthreads(); }
    g_w[bh * NS + k] = e / red[0];
}

// =====================================================================
// Fused attention (fp32, unchanged from working R3 kernel)
// =====================================================================
#define S_LD 516
#define SM_S    (64 * S_LD)
#define SM_QS   (64 * 68)
#define SM_KS   (64 * 132)
#define SM_W    512
#define SMEM_FLOATS (SM_S + SM_QS + SM_KS + SM_W)
#define SMEM_BYTES  (SMEM_FLOATS * 4)

__global__ void attn_fused(const float* __restrict__ gate) {
    extern __shared__ float sm[];
    float* S = sm;
    float (*Qs)[68]  = (float(*)[68]) (sm + SM_S);
    float (*Ks)[132] = (float(*)[132])(sm + SM_S + SM_QS);
    float (*Vs)[68]  = (float(*)[68]) (sm + SM_S + SM_QS);
    float* wrow = sm + SM_S + SM_QS + SM_KS;

    int tid = threadIdx.x;
    int bh = blockIdx.y;
    int q0 = blockIdx.x * 64;
    int h = bh & 7;
    int b = bh >> 3;
    const float* Qg = g_q + (size_t)bh * NS * NDH;
    const float* Kg = g_k + (size_t)bh * NS * NDH;
    const float* Vg = g_v + (size_t)bh * NS * NDH;

    float gv = 1.0f / (1.0f + __expf(-gate[h]));
    float og = 1.0f - gv;

    {
        int q = tid >> 2;
        int d0 = (tid & 3) * 16;
        #pragma unroll
        for (int c = 0; c < 4; c++) {
            float4 v = *(const float4*)&Qg[(q0 + q) * NDH + d0 + c * 4];
            Qs[d0 + c * 4 + 0][q] = v.x;
            Qs[d0 + c * 4 + 1][q] = v.y;
            Qs[d0 + c * 4 + 2][q] = v.z;
            Qs[d0 + c * 4 + 3][q] = v.w;
        }
        wrow[tid]       = g_w[bh * NS + tid];
        wrow[tid + 256] = g_w[bh * NS + tid + 256];
    }
    __syncthreads();

    int tx = tid & 15, ty = tid >> 4;

    for (int kc = 0; kc < 4; kc++) {
        {
            int kr = tid >> 1;
            int dbase = (tid & 1) * 32;
            #pragma unroll
            for (int c = 0; c < 8; c++) {
                float4 v = *(const float4*)&Kg[(kc * 128 + kr) * NDH + dbase + c * 4];
                Ks[dbase + c * 4 + 0][kr] = v.x;
                Ks[dbase + c * 4 + 1][kr] = v.y;
                Ks[dbase + c * 4 + 2][kr] = v.z;
                Ks[dbase + c * 4 + 3][kr] = v.w;
            }
        }
        __syncthreads();
        float acc[4][8] = {};
        #pragma unroll
        for (int d = 0; d < 64; d++) {
            float4 a  = *(float4*)&Qs[d][ty * 4];
            float4 b0 = *(float4*)&Ks[d][tx * 4];
            float4 b1 = *(float4*)&Ks[d][64 + tx * 4];
            float av[4] = {a.x, a.y, a.z, a.w};
            float bv[8] = {b0.x, b0.y, b0.z, b0.w, b1.x, b1.y, b1.z, b1.w};
            #pragma unroll
            for (int i = 0; i < 4; i++)
                #pragma unroll
                for (int j = 0; j < 8; j++)
                    acc[i][j] += av[i] * bv[j];
        }
        #pragma unroll
        for (int i = 0; i < 4; i++) {
            int r = ty * 4 + i;
            float4 v0 = make_float4(acc[i][0] * 0.125f, acc[i][1] * 0.125f,
                                    acc[i][2] * 0.125f, acc[i][3] * 0.125f);
            float4 v1 = make_float4(acc[i][4] * 0.125f, acc[i][5] * 0.125f,
                                    acc[i][6] * 0.125f, acc[i][7] * 0.125f);
            *(float4*)&S[r * S_LD + kc * 128 + tx * 4]      = v0;
            *(float4*)&S[r * S_LD + kc * 128 + 64 + tx * 4] = v1;
        }
        __syncthreads();
    }

    {
        int lane = tid & 31;
        int w = tid >> 5;
        for (int rr = 0; rr < 8; rr++) {
            float* row = S + (w * 8 + rr) * S_LD;
            float m = -1e30f;
            #pragma unroll
            for (int i = 0; i < 16; i++) m = fmaxf(m, row[lane + 32 * i]);
            #pragma unroll
            for (int off = 16; off > 0; off >>= 1)
                m = fmaxf(m, __shfl_xor_sync(0xFFFFFFFF, m, off));
            float s = 0.0f;
            #pragma unroll
            for (int i = 0; i < 16; i++) {
                float e = __expf(row[lane + 32 * i] - m);
                row[lane + 32 * i] = e;
                s += e;
            }
            #pragma unroll
            for (int off = 16; off > 0; off >>= 1)
                s += __shfl_xor_sync(0xFFFFFFFF, s, off);
            float inv = og / s;
            #pragma unroll
            for (int i = 0; i < 16; i++) {
                int idx = lane + 32 * i;
                row[idx] = row[idx] * inv + gv * wrow[idx];
            }
        }
    }
    __syncthreads();

    float o[4][4] = {};
    for (int vc = 0; vc < 8; vc++) {
        {
            int kk = tid >> 2;
            int d0 = (tid & 3) * 16;
            #pragma unroll
            for (int c = 0; c < 4; c++)
                *(float4*)&Vs[kk][d0 + c * 4] =
                    *(const float4*)&Vg[(vc * 64 + kk) * NDH + d0 + c * 4];
        }
        __syncthreads();
        #pragma unroll
        for (int k4 = 0; k4 < 64; k4 += 4) {
            float4 ar[4];
            #pragma unroll
            for (int i = 0; i < 4; i++)
                ar[i] = *(float4*)&S[(ty * 4 + i) * S_LD + vc * 64 + k4];
            float a[4][4] = {{ar[0].x, ar[0].y, ar[0].z, ar[0].w},
                             {ar[1].x, ar[1].y, ar[1].z, ar[1].w},
                             {ar[2].x, ar[2].y, ar[2].z, ar[2].w},
                             {ar[3].x, ar[3].y, ar[3].z, ar[3].w}};
            #pragma unroll
            for (int kk = 0; kk < 4; kk++) {
                float4 bv = *(float4*)&Vs[k4 + kk][tx * 4];
                float bb[4] = {bv.x, bv.y, bv.z, bv.w};
                #pragma unroll
                for (int i = 0; i < 4; i++)
                    #pragma unroll
                    for (int j = 0; j < 4; j++)
                        o[i][j] += a[i][kk] * bb[j];
            }
        }
        __syncthreads();
    }
    #pragma unroll
    for (int i = 0; i < 4; i++) {
        int q = q0 + ty * 4 + i;
        float4 v = make_float4(o[i][0], o[i][1], o[i][2], o[i][3]);
        *(float4*)&g_y[((size_t)b * NS + q) * NDIM + h * NDH + tx * 4] = v;
    }
}

extern "C" void kernel_launch(void* const* d_in, const int* in_sizes, int n_in,
                              void* d_out, int out_size) {
    const float* x    = (const float*)d_in[0];
    const float* pos  = (const float*)d_in[1];
    const float* Wq   = (const float*)d_in[2];
    const float* Wk   = (const float*)d_in[3];
    const float* Wv   = (const float*)d_in[4];
    const float* Wo   = (const float*)d_in[5];
    const float* bo   = (const float*)d_in[6];
    const float* Wp1  = (const float*)d_in[7];
    const float* bp1  = (const float*)d_in[8];
    const float* Wp2  = (const float*)d_in[9];
    const float* bp2  = (const float*)d_in[10];
    const float* Wh   = (const float*)d_in[11];
    // d_in[12] = bh : cancels inside softmax (constant along k axis) — unused
    const float* gate = (const float*)d_in[13];
    float* out = (float*)d_out;

    static bool attr_set = false;
    if (!attr_set) {
        cudaFuncSetAttribute(attn_fused, cudaFuncAttributeMaxDynamicSharedMemorySize, SMEM_BYTES);
        cudaFuncSetAttribute(qkv_tf32, cudaFuncAttributeMaxDynamicSharedMemorySize, TF32_SMEM_BYTES);
        cudaFuncSetAttribute(out_tf32, cudaFuncAttributeMaxDynamicSharedMemorySize, TF32_SMEM_BYTES);
        attr_set = true;
    }

    u_kernel<<<8, 256>>>(pos, Wp1, bp1, Wp2, bp2, Wh);
    pos_w_kernel<<<32, 512>>>();
    qkv_tf32<<<dim3(4, 16, 3), 256, TF32_SMEM_BYTES>>>(x, Wq, Wk, Wv);
    attn_fused<<<dim3(8, 32), 256, SMEM_BYTES>>>(gate);
    out_tf32<<<dim3(4, 16), 256, TF32_SMEM_BYTES>>>(Wo, bo, out);
}

// round 5
// speedup vs baseline: 1.1646x; 1.1646x over previous
#include <cuda_runtime.h>
#include <math.h>

#define NB 4
#define NS 512
#define NDIM 512
#define NH 8
#define NDH 64
#define NM (NB*NS)     // 2048

// ---------------- device scratch (no allocations allowed) ----------------
__device__ float g_q[NB*NH*NS*NDH];     // [b][h][s][d]
__device__ float g_k[NB*NH*NS*NDH];
__device__ float g_v[NB*NH*NS*NDH];
__device__ float g_u[NB*NS*NH];         // [b][s][h]
__device__ float g_w[NB*NH*NS];         // [b][h][k] : q-independent positional attn row
__device__ float g_opos[NB*NH*NDH];     // [b][h][d] : w @ V   (positional output term)
__device__ float g_y[NM*NDIM];          // pre-output-projection activations

// =====================================================================
// 128x128 block-tile fp32 GEMM core, 8x8 per thread, 256 threads.
// =====================================================================
__device__ __forceinline__ void gemm128_core(const float* __restrict__ A, int lda,
                                             const float* __restrict__ B, int ldb,
                                             int K, float (&acc)[8][8],
                                             float (*As)[132], float (*Bs)[128]) {
    int tid = threadIdx.x;
    int tx = tid & 15, ty = tid >> 4;
    int arow = tid >> 1, acol = (tid & 1) * 8;   // 128 rows x 16 k, 8 floats/thread
    int brow = tid >> 4, bcol = (tid & 15) * 8;  // 16 k x 128 n

    for (int k0 = 0; k0 < K; k0 += 16) {
        float4 av0 = *(const float4*)&A[arow * lda + k0 + acol];
        float4 av1 = *(const float4*)&A[arow * lda + k0 + acol + 4];
        As[acol + 0][arow] = av0.x;
        As[acol + 1][arow] = av0.y;
        As[acol + 2][arow] = av0.z;
        As[acol + 3][arow] = av0.w;
        As[acol + 4][arow] = av1.x;
        As[acol + 5][arow] = av1.y;
        As[acol + 6][arow] = av1.z;
        As[acol + 7][arow] = av1.w;
        *(float4*)&Bs[brow][bcol]     = *(const float4*)&B[(k0 + brow) * ldb + bcol];
        *(float4*)&Bs[brow][bcol + 4] = *(const float4*)&B[(k0 + brow) * ldb + bcol + 4];
        __syncthreads();
        #pragma unroll
        for (int kk = 0; kk < 16; kk++) {
            float4 a0 = *(float4*)&As[kk][ty * 4];
            float4 a1 = *(float4*)&As[kk][64 + ty * 4];
            float4 b0 = *(float4*)&Bs[kk][tx * 4];
            float4 b1 = *(float4*)&Bs[kk][64 + tx * 4];
            float a[8] = {a0.x, a0.y, a0.z, a0.w, a1.x, a1.y, a1.z, a1.w};
            float b[8] = {b0.x, b0.y, b0.z, b0.w, b1.x, b1.y, b1.z, b1.w};
            #pragma unroll
            for (int i = 0; i < 8; i++)
                #pragma unroll
                for (int j = 0; j < 8; j++)
                    acc[i][j] += a[i] * b[j];
        }
        __syncthreads();
    }
}

// ---------------- QKV projection with scatter to [b,h,s,d] ----------------
__global__ void qkv_gemm(const float* __restrict__ X, const float* __restrict__ Wq,
                         const float* __restrict__ Wk, const float* __restrict__ Wv) {
    __shared__ float As[16][132];
    __shared__ float Bs[16][128];
    const float* W = (blockIdx.z == 0) ? Wq : ((blockIdx.z == 1) ? Wk : Wv);
    float* out = (blockIdx.z == 0) ? g_q : ((blockIdx.z == 1) ? g_k : g_v);
    int m0 = blockIdx.y * 128, n0 = blockIdx.x * 128;
    float acc[8][8] = {};
    gemm128_core(X + m0 * NDIM, NDIM, W + n0, NDIM, NDIM, acc, As, Bs);
    int tx = threadIdx.x & 15, ty = threadIdx.x >> 4;
    #pragma unroll
    for (int i = 0; i < 8; i++) {
        int m = m0 + ((i < 4) ? ty * 4 + i : 64 + ty * 4 + (i - 4));
        int b = m >> 9, s = m & 511;
        #pragma unroll
        for (int jh = 0; jh < 2; jh++) {
            int n = n0 + (jh ? 64 + tx * 4 : tx * 4);
            int h = n >> 6, d = n & 63;
            float4 v = make_float4(acc[i][jh * 4 + 0], acc[i][jh * 4 + 1],
                                   acc[i][jh * 4 + 2], acc[i][jh * 4 + 3]);
            *(float4*)&out[((b * NH + h) * NS + s) * NDH + d] = v;
        }
    }
}

// ---------------- out = y @ Wo + bo ----------------
__global__ void out_gemm(const float* __restrict__ Wo, const float* __restrict__ bo,
                         float* __restrict__ out) {
    __shared__ float As[16][132];
    __shared__ float Bs[16][128];
    int m0 = blockIdx.y * 128, n0 = blockIdx.x * 128;
    float acc[8][8] = {};
    gemm128_core(g_y + m0 * NDIM, NDIM, Wo + n0, NDIM, NDIM, acc, As, Bs);
    int tx = threadIdx.x & 15, ty = threadIdx.x >> 4;
    #pragma unroll
    for (int i = 0; i < 8; i++) {
        int m = m0 + ((i < 4) ? ty * 4 + i : 64 + ty * 4 + (i - 4));
        #pragma unroll
        for (int jh = 0; jh < 2; jh++) {
            int n = n0 + (jh ? 64 + tx * 4 : tx * 4);
            float4 v = make_float4(acc[i][jh * 4 + 0] + bo[n + 0], acc[i][jh * 4 + 1] + bo[n + 1],
                                   acc[i][jh * 4 + 2] + bo[n + 2], acc[i][jh * 4 + 3] + bo[n + 3]);
            *(float4*)&out[m * NDIM + n] = v;
        }
    }
}

// ---------------- tiny positional MLP: u[b,s,h] ----------------
__global__ void u_kernel(const float* __restrict__ pos,
                         const float* __restrict__ Wp1, const float* __restrict__ bp1,
                         const float* __restrict__ Wp2, const float* __restrict__ bp2,
                         const float* __restrict__ Wh) {
    int idx = blockIdx.x * blockDim.x + threadIdx.x;
    if (idx >= NM) return;
    const float* pp = pos + idx * 3;
    float p0 = pp[0], p1 = pp[1], p2 = pp[2];
    float h1[3];
    #pragma unroll
    for (int j = 0; j < 3; j++)
        h1[j] = fmaxf(0.0f, p0 * Wp1[j] + p1 * Wp1[3 + j] + p2 * Wp1[6 + j] + bp1[j]);
    float u[NH];
    #pragma unroll
    for (int hh = 0; hh < NH; hh++) u[hh] = 0.0f;
    for (int j = 0; j < 64; j++) {
        float pv = h1[0] * Wp2[j] + h1[1] * Wp2[64 + j] + h1[2] * Wp2[128 + j] + bp2[j];
        #pragma unroll
        for (int hh = 0; hh < NH; hh++) u[hh] += pv * Wh[j * NH + hh];
    }
    #pragma unroll
    for (int hh = 0; hh < NH; hh++) g_u[idx * NH + hh] = u[hh];
}

// w[b,h,k] = softmax_k(-u[b,k,h])
__global__ void pos_w_kernel() {
    __shared__ float red[512];
    int bh = blockIdx.x;
    int b = bh >> 3, h = bh & 7;
    int k = threadIdx.x;
    float t = -g_u[(b * NS + k) * NH + h];
    red[k] = t; __syncthreads();
    for (int s = 256; s > 0; s >>= 1) { if (k < s) red[k] = fmaxf(red[k], red[k + s]); __syncthreads(); }
    float m = red[0]; __syncthreads();
    float e = expf(t - m);
    red[k] = e; __syncthreads();
    for (int s = 256; s > 0; s >>= 1) { if (k < s) red[k] += red[k + s]; __syncthreads(); }
    g_w[bh * NS + k] = e / red[0];
}

// O_pos[bh][d] = sum_k w[bh][k] * V[bh][k][d]   (tiny GEMV per bh)
__global__ void opos_kernel() {
    __shared__ float part[4][64];
    int bh = blockIdx.x;
    int d = threadIdx.x & 63;
    int ks = threadIdx.x >> 6;          // 4 k-slices of 128
    const float* V = g_v + (size_t)bh * NS * NDH;
    const float* w = g_w + bh * NS;
    float s = 0.0f;
    for (int k = ks * 128; k < (ks + 1) * 128; k++)
        s += w[k] * V[k * NDH + d];
    part[ks][d] = s;
    __syncthreads();
    if (threadIdx.x < 64)
        g_opos[bh * NDH + d] = part[0][d] + part[1][d] + part[2][d] + part[3][d];
}

// =====================================================================
// Flash attention per (bh, 64-q tile): online softmax, no full S row.
// out = og * softmax(QK^T/8) @ V + gv * O_pos  (positional term q-indep)
// smem: Qs/Ks [d][*] transposed, Vs [k][d], Ps [q][k] round-trip. ~70KB.
// =====================================================================
#define FLASH_SMEM_FLOATS (4 * 64 * 68 + 64)
#define FLASH_SMEM_BYTES  (FLASH_SMEM_FLOATS * 4)   // 69,888

__global__ void __launch_bounds__(256, 3)
attn_flash(const float* __restrict__ gate) {
    extern __shared__ float sm[];
    float (*Qs)[68] = (float(*)[68])(sm);
    float (*Ks)[68] = (float(*)[68])(sm + 4352);
    float (*Vs)[68] = (float(*)[68])(sm + 8704);
    float (*Ps)[68] = (float(*)[68])(sm + 13056);
    float* opos_s = sm + 17408;

    int tid = threadIdx.x;
    int bh = blockIdx.y;
    int q0 = blockIdx.x * 64;
    int h = bh & 7, b = bh >> 3;
    const float* Qg = g_q + (size_t)bh * NS * NDH;
    const float* Kg = g_k + (size_t)bh * NS * NDH;
    const float* Vg = g_v + (size_t)bh * NS * NDH;

    float gv = 1.0f / (1.0f + __expf(-gate[h]));
    float og = 1.0f - gv;

    // load Q tile transposed: Qs[d][q]
    int r4 = tid >> 2;                 // 0..63
    int d0 = (tid & 3) * 16;
    #pragma unroll
    for (int c = 0; c < 4; c++) {
        float4 v = *(const float4*)&Qg[(q0 + r4) * NDH + d0 + c * 4];
        Qs[d0 + c * 4 + 0][r4] = v.x;
        Qs[d0 + c * 4 + 1][r4] = v.y;
        Qs[d0 + c * 4 + 2][r4] = v.z;
        Qs[d0 + c * 4 + 3][r4] = v.w;
    }
    if (tid < 64) opos_s[tid] = g_opos[bh * NDH + tid];
    __syncthreads();

    int tx = tid & 15, ty = tid >> 4;
    float o[4][4] = {};
    float mrow[4], lrow[4];
    #pragma unroll
    for (int i = 0; i < 4; i++) { mrow[i] = -1e30f; lrow[i] = 0.0f; }

    for (int kc = 0; kc < 8; kc++) {
        // load K chunk transposed Ks[d][kr] and V chunk Vs[kr][d]
        #pragma unroll
        for (int c = 0; c < 4; c++) {
            float4 v = *(const float4*)&Kg[(kc * 64 + r4) * NDH + d0 + c * 4];
            Ks[d0 + c * 4 + 0][r4] = v.x;
            Ks[d0 + c * 4 + 1][r4] = v.y;
            Ks[d0 + c * 4 + 2][r4] = v.z;
            Ks[d0 + c * 4 + 3][r4] = v.w;
            *(float4*)&Vs[r4][d0 + c * 4] =
                *(const float4*)&Vg[(kc * 64 + r4) * NDH + d0 + c * 4];
        }
        __syncthreads();

        // S chunk [4q][4k] per thread
        float s[4][4] = {};
        #pragma unroll
        for (int d = 0; d < 64; d++) {
            float4 a  = *(float4*)&Qs[d][ty * 4];
            float4 bv = *(float4*)&Ks[d][tx * 4];
            float av[4] = {a.x, a.y, a.z, a.w};
            float bb[4] = {bv.x, bv.y, bv.z, bv.w};
            #pragma unroll
            for (int i = 0; i < 4; i++)
                #pragma unroll
                for (int j = 0; j < 4; j++)
                    s[i][j] += av[i] * bb[j];
        }

        // online softmax update per row (reduce over 16 tx lanes)
        #pragma unroll
        for (int i = 0; i < 4; i++) {
            float mx = fmaxf(fmaxf(s[i][0], s[i][1]), fmaxf(s[i][2], s[i][3])) * 0.125f;
            #pragma unroll
            for (int off = 1; off < 16; off <<= 1)
                mx = fmaxf(mx, __shfl_xor_sync(0xFFFFFFFF, mx, off));
            float mn = fmaxf(mrow[i], mx);
            float alpha = __expf(mrow[i] - mn);
            float rs = 0.0f;
            #pragma unroll
            for (int j = 0; j < 4; j++) {
                float p = __expf(s[i][j] * 0.125f - mn);
                s[i][j] = p;
                rs += p;
            }
            #pragma unroll
            for (int off = 1; off < 16; off <<= 1)
                rs += __shfl_xor_sync(0xFFFFFFFF, rs, off);
            lrow[i] = lrow[i] * alpha + rs;
            mrow[i] = mn;
            #pragma unroll
            for (int j = 0; j < 4; j++) o[i][j] *= alpha;
            *(float4*)&Ps[ty * 4 + i][tx * 4] = make_float4(s[i][0], s[i][1], s[i][2], s[i][3]);
        }
        __syncthreads();

        // o += P @ V_chunk
        #pragma unroll
        for (int k4 = 0; k4 < 64; k4 += 4) {
            float4 ar[4];
            #pragma unroll
            for (int i = 0; i < 4; i++)
                ar[i] = *(float4*)&Ps[ty * 4 + i][k4];
            float a[4][4] = {{ar[0].x, ar[0].y, ar[0].z, ar[0].w},
                             {ar[1].x, ar[1].y, ar[1].z, ar[1].w},
                             {ar[2].x, ar[2].y, ar[2].z, ar[2].w},
                             {ar[3].x, ar[3].y, ar[3].z, ar[3].w}};
            #pragma unroll
            for (int kk = 0; kk < 4; kk++) {
                float4 bv = *(float4*)&Vs[k4 + kk][tx * 4];
                float bb[4] = {bv.x, bv.y, bv.z, bv.w};
                #pragma unroll
                for (int i = 0; i < 4; i++)
                    #pragma unroll
                    for (int j = 0; j < 4; j++)
                        o[i][j] += a[i][kk] * bb[j];
            }
        }
        __syncthreads();
    }

    // epilogue: out = og * o / l + gv * O_pos
    #pragma unroll
    for (int i = 0; i < 4; i++) {
        int q = q0 + ty * 4 + i;
        float f = og / lrow[i];
        float4 v = make_float4(o[i][0] * f + gv * opos_s[tx * 4 + 0],
                               o[i][1] * f + gv * opos_s[tx * 4 + 1],
                               o[i][2] * f + gv * opos_s[tx * 4 + 2],
                               o[i][3] * f + gv * opos_s[tx * 4 + 3]);
        *(float4*)&g_y[((size_t)b * NS + q) * NDIM + h * NDH + tx * 4] = v;
    }
}

extern "C" void kernel_launch(void* const* d_in, const int* in_sizes, int n_in,
                              void* d_out, int out_size) {
    const float* x    = (const float*)d_in[0];
    const float* pos  = (const float*)d_in[1];
    const float* Wq   = (const float*)d_in[2];
    const float* Wk   = (const float*)d_in[3];
    const float* Wv   = (const float*)d_in[4];
    const float* Wo   = (const float*)d_in[5];
    const float* bo   = (const float*)d_in[6];
    const float* Wp1  = (const float*)d_in[7];
    const float* bp1  = (const float*)d_in[8];
    const float* Wp2  = (const float*)d_in[9];
    const float* bp2  = (const float*)d_in[10];
    const float* Wh   = (const float*)d_in[11];
    // d_in[12] = bh : cancels inside softmax (constant along k axis) — unused
    const float* gate = (const float*)d_in[13];
    float* out = (float*)d_out;

    static bool attr_set = false;
    if (!attr_set) {
        cudaFuncSetAttribute(attn_flash, cudaFuncAttributeMaxDynamicSharedMemorySize, FLASH_SMEM_BYTES);
        attr_set = true;
    }

    u_kernel<<<8, 256>>>(pos, Wp1, bp1, Wp2, bp2, Wh);
    pos_w_kernel<<<32, 512>>>();
    qkv_gemm<<<dim3(4, 16, 3), 256>>>(x, Wq, Wk, Wv);
    opos_kernel<<<32, 256>>>();
    attn_flash<<<dim3(8, 32), 256, FLASH_SMEM_BYTES>>>(gate);
    out_gemm<<<dim3(4, 16), 256>>>(Wo, bo, out);
}

// round 6
// speedup vs baseline: 1.2938x; 1.1109x over previous
#include <cuda_runtime.h>
#include <math.h>

#define NB 4
#define NS 512
#define NDIM 512
#define NH 8
#define NDH 64
#define NM (NB*NS)     // 2048

// ---------------- device scratch (no allocations allowed) ----------------
__device__ float g_q[NB*NH*NS*NDH];     // [b][h][s][d]
__device__ float g_k[NB*NH*NS*NDH];
__device__ float g_v[NB*NH*NS*NDH];
__device__ float g_u[NB*NS*NH];         // [b][s][h]
__device__ float g_w[NB*NH*NS];         // [b][h][k]
__device__ float g_opos[NB*NH*NDH];     // [b][h][d] : w @ V
__device__ float g_y[NM*NDIM];          // pre-output-projection activations

// tf32 hi/lo pre-split, pre-permuted into mma fragment order:
// A-side (X or y), [mblk(128)][kblk(64)][lane(32)][reg(4)]
__device__ float g_xh[NM*NDIM], g_xl[NM*NDIM];
__device__ float g_yh[NM*NDIM], g_yl[NM*NDIM];
// B-side (weights), per matrix [kblk(64)][nblk(64)][lane(32)][reg(2)]; mat: 0=Wq 1=Wk 2=Wv 3=Wo
__device__ float g_wh[4*NDIM*NDIM], g_wl[4*NDIM*NDIM];

__device__ __forceinline__ unsigned f2tf(float x) {
    unsigned r;
    asm("cvt.rna.tf32.f32 %0, %1;" : "=r"(r) : "f"(x));
    return r;
}

__device__ __forceinline__ void mma_tf32(float (&d)[4], const unsigned (&a)[4],
                                         unsigned b0, unsigned b1) {
    asm volatile(
        "mma.sync.aligned.m16n8k8.row.col.f32.tf32.tf32.f32 "
        "{%0,%1,%2,%3}, {%4,%5,%6,%7}, {%8,%9}, {%0,%1,%2,%3};"
        : "+f"(d[0]), "+f"(d[1]), "+f"(d[2]), "+f"(d[3])
        : "r"(a[0]), "r"(a[1]), "r"(a[2]), "r"(a[3]), "r"(b0), "r"(b1));
}

// ---------------- split kernels (one-time per launch, streaming) ----------
// A-side: row m of src [2048x512] -> fragment layout
__device__ __forceinline__ void split_arow(const float* __restrict__ src,
                                           float* __restrict__ dh, float* __restrict__ dl,
                                           int m) {
    int tid = threadIdx.x;            // 128 threads, 4 k each
    int mblk = m >> 4, mr = m & 15;
    int k0 = tid * 4;
    float4 v = *(const float4*)&src[m * NDIM + k0];
    float vv[4] = {v.x, v.y, v.z, v.w};
    #pragma unroll
    for (int e = 0; e < 4; e++) {
        int k = k0 + e;
        int kblk = k >> 3, kc = k & 7;
        int reg = ((mr >> 3) & 1) | ((kc >> 2) << 1);
        int lane = (mr & 7) * 4 + (kc & 3);
        int idx = ((mblk * 64 + kblk) * 32 + lane) * 4 + reg;
        float hi = __uint_as_float(f2tf(vv[e]));
        dh[idx] = hi;
        dl[idx] = __uint_as_float(f2tf(vv[e] - hi));
    }
}

__global__ void split_x_kernel(const float* __restrict__ X) {
    split_arow(X, g_xh, g_xl, blockIdx.x);
}
__global__ void split_y_kernel() {
    split_arow(g_y, g_yh, g_yl, blockIdx.x);
}

// B-side: (matrix, k-row) per block; threads cover n
__global__ void split_w_kernel(const float* __restrict__ Wq, const float* __restrict__ Wk,
                               const float* __restrict__ Wv, const float* __restrict__ Wo) {
    int mat = blockIdx.x >> 9;        // 0..3
    int k = blockIdx.x & 511;
    const float* W = (mat == 0) ? Wq : (mat == 1) ? Wk : (mat == 2) ? Wv : Wo;
    float* dh = g_wh + mat * NDIM * NDIM;
    float* dl = g_wl + mat * NDIM * NDIM;
    int kblk = k >> 3, kc = k & 7;
    int reg = (kc >> 2) & 1, tl = kc & 3;
    int n0 = threadIdx.x * 4;         // 128 threads
    float4 v = *(const float4*)&W[k * NDIM + n0];
    float vv[4] = {v.x, v.y, v.z, v.w};
    #pragma unroll
    for (int e = 0; e < 4; e++) {
        int n = n0 + e;
        int nblk = n >> 3, nc = n & 7;
        int lane = nc * 4 + tl;
        int idx = ((kblk * 64 + nblk) * 32 + lane) * 2 + reg;
        float hi = __uint_as_float(f2tf(vv[e]));
        dh[idx] = hi;
        dl[idx] = __uint_as_float(f2tf(vv[e] - hi));
    }
}

// =====================================================================
// tf32 x3 MMA GEMM, 128x128 tile, 8 warps (warp = 32m x 64n), no smem.
// Fragments streamed straight from pre-permuted gmem.
// =====================================================================
__device__ __forceinline__ void mma_gemm_tile(const float* __restrict__ Ah,
                                              const float* __restrict__ Al,
                                              const float* __restrict__ Bh,
                                              const float* __restrict__ Bl,
                                              int mblk0, int nblk0,
                                              float (&acc)[2][8][4]) {
    int lane = threadIdx.x & 31, wid = threadIdx.x >> 5;
    int warp_m = wid >> 1, warp_n = wid & 1;
    int gmb0 = mblk0 + warp_m * 2;
    int gnb0 = nblk0 + warp_n * 8;

    #pragma unroll 2
    for (int kb = 0; kb < 64; kb++) {
        unsigned ah[2][4], al[2][4];
        #pragma unroll
        for (int mb2 = 0; mb2 < 2; mb2++) {
            const float4 h4 = *(const float4*)&Ah[(((gmb0 + mb2) * 64 + kb) * 32 + lane) * 4];
            const float4 l4 = *(const float4*)&Al[(((gmb0 + mb2) * 64 + kb) * 32 + lane) * 4];
            ah[mb2][0] = __float_as_uint(h4.x); ah[mb2][1] = __float_as_uint(h4.y);
            ah[mb2][2] = __float_as_uint(h4.z); ah[mb2][3] = __float_as_uint(h4.w);
            al[mb2][0] = __float_as_uint(l4.x); al[mb2][1] = __float_as_uint(l4.y);
            al[mb2][2] = __float_as_uint(l4.z); al[mb2][3] = __float_as_uint(l4.w);
        }
        #pragma unroll
        for (int nb = 0; nb < 8; nb++) {
            const float2 h2 = *(const float2*)&Bh[((kb * 64 + gnb0 + nb) * 32 + lane) * 2];
            const float2 l2 = *(const float2*)&Bl[((kb * 64 + gnb0 + nb) * 32 + lane) * 2];
            unsigned b0h = __float_as_uint(h2.x), b1h = __float_as_uint(h2.y);
            unsigned b0l = __float_as_uint(l2.x), b1l = __float_as_uint(l2.y);
            #pragma unroll
            for (int mb2 = 0; mb2 < 2; mb2++) {
                mma_tf32(acc[mb2][nb], ah[mb2], b0h, b1h);
                mma_tf32(acc[mb2][nb], ah[mb2], b0l, b1l);
                mma_tf32(acc[mb2][nb], al[mb2], b0h, b1h);
            }
        }
    }
}

// ---------------- QKV projection (tf32 mma), scatter to [b,h,s,d] --------
__global__ void __launch_bounds__(256, 2)
qkv_mma() {
    int mat = blockIdx.z;                    // 0=q 1=k 2=v
    float* out = (mat == 0) ? g_q : (mat == 1) ? g_k : g_v;
    const float* Bh = g_wh + mat * NDIM * NDIM;
    const float* Bl = g_wl + mat * NDIM * NDIM;
    int m0 = blockIdx.y * 128, n0 = blockIdx.x * 128;
    float acc[2][8][4] = {};
    mma_gemm_tile(g_xh, g_xl, Bh, Bl, m0 >> 4, n0 >> 3, acc);

    int lane = threadIdx.x & 31, wid = threadIdx.x >> 5;
    int warp_m = wid >> 1, warp_n = wid & 1;
    int g = lane >> 2, t = lane & 3;
    #pragma unroll
    for (int mb2 = 0; mb2 < 2; mb2++) {
        int mrow = m0 + warp_m * 32 + mb2 * 16 + g;
        #pragma unroll
        for (int nb = 0; nb < 8; nb++) {
            int ncol = n0 + (warp_n * 8 + nb) * 8 + 2 * t;
            int h = ncol >> 6, d = ncol & 63;
            {
                int b = mrow >> 9, s = mrow & 511;
                *(float2*)&out[((b * NH + h) * NS + s) * NDH + d] =
                    make_float2(acc[mb2][nb][0], acc[mb2][nb][1]);
            }
            {
                int m2 = mrow + 8;
                int b = m2 >> 9, s = m2 & 511;
                *(float2*)&out[((b * NH + h) * NS + s) * NDH + d] =
                    make_float2(acc[mb2][nb][2], acc[mb2][nb][3]);
            }
        }
    }
}

// ---------------- out = y @ Wo + bo (tf32 mma) ----------------
__global__ void __launch_bounds__(256, 2)
out_mma(const float* __restrict__ bo, float* __restrict__ out) {
    const float* Bh = g_wh + 3 * NDIM * NDIM;
    const float* Bl = g_wl + 3 * NDIM * NDIM;
    int m0 = blockIdx.y * 128, n0 = blockIdx.x * 128;
    float acc[2][8][4] = {};
    mma_gemm_tile(g_yh, g_yl, Bh, Bl, m0 >> 4, n0 >> 3, acc);

    int lane = threadIdx.x & 31, wid = threadIdx.x >> 5;
    int warp_m = wid >> 1, warp_n = wid & 1;
    int g = lane >> 2, t = lane & 3;
    #pragma unroll
    for (int mb2 = 0; mb2 < 2; mb2++) {
        int mrow = m0 + warp_m * 32 + mb2 * 16 + g;
        #pragma unroll
        for (int nb = 0; nb < 8; nb++) {
            int ncol = n0 + (warp_n * 8 + nb) * 8 + 2 * t;
            float b0 = bo[ncol], b1 = bo[ncol + 1];
            *(float2*)&out[(size_t)mrow * NDIM + ncol] =
                make_float2(acc[mb2][nb][0] + b0, acc[mb2][nb][1] + b1);
            *(float2*)&out[(size_t)(mrow + 8) * NDIM + ncol] =
                make_float2(acc[mb2][nb][2] + b0, acc[mb2][nb][3] + b1);
        }
    }
}

// ---------------- tiny positional MLP: u[b,s,h]; also zero g_opos --------
__global__ void u_kernel(const float* __restrict__ pos,
                         const float* __restrict__ Wp1, const float* __restrict__ bp1,
                         const float* __restrict__ Wp2, const float* __restrict__ bp2,
                         const float* __restrict__ Wh) {
    int idx = blockIdx.x * blockDim.x + threadIdx.x;
    if (idx >= NM) return;
    g_opos[idx & (NB*NH*NDH - 1)] = 0.0f;   // NM == NB*NH*NDH == 2048
    const float* pp = pos + idx * 3;
    float p0 = pp[0], p1 = pp[1], p2 = pp[2];
    float h1[3];
    #pragma unroll
    for (int j = 0; j < 3; j++)
        h1[j] = fmaxf(0.0f, p0 * Wp1[j] + p1 * Wp1[3 + j] + p2 * Wp1[6 + j] + bp1[j]);
    float u[NH];
    #pragma unroll
    for (int hh = 0; hh < NH; hh++) u[hh] = 0.0f;
    for (int j = 0; j < 64; j++) {
        float pv = h1[0] * Wp2[j] + h1[1] * Wp2[64 + j] + h1[2] * Wp2[128 + j] + bp2[j];
        #pragma unroll
        for (int hh = 0; hh < NH; hh++) u[hh] += pv * Wh[j * NH + hh];
    }
    #pragma unroll
    for (int hh = 0; hh < NH; hh++) g_u[idx * NH + hh] = u[hh];
}

// w[b,h,k] = softmax_k(-u[b,k,h])
__global__ void pos_w_kernel() {
    __shared__ float red[512];
    int bh = blockIdx.x;
    int b = bh >> 3, h = bh & 7;
    int k = threadIdx.x;
    float t = -g_u[(b * NS + k) * NH + h];
    red[k] = t; __syncthreads();
    for (int s = 256; s > 0; s >>= 1) { if (k < s) red[k] = fmaxf(red[k], red[k + s]); __syncthreads(); }
    float m = red[0]; __syncthreads();
    float e = expf(t - m);
    red[k] = e; __syncthreads();
    for (int s = 256; s > 0; s >>= 1) { if (k < s) red[k] += red[k + s]; __syncthreads(); }
    g_w[bh * NS + k] = e / red[0];
}

// O_pos[bh][d] += partial(w @ V) : split-K over 4 CTAs per bh
__global__ void opos_kernel() {
    __shared__ float part[4][64];
    int bh = blockIdx.x;
    int kq = blockIdx.y;                 // k quarter: 128 rows
    int d = threadIdx.x & 63;
    int ks = threadIdx.x >> 6;           // 4 sub-slices of 32
    const float* V = g_v + (size_t)bh * NS * NDH;
    const float* w = g_w + bh * NS;
    int kbase = kq * 128 + ks * 32;
    float s = 0.0f;
    #pragma unroll 4
    for (int k = kbase; k < kbase + 32; k++)
        s += w[k] * V[k * NDH + d];
    part[ks][d] = s;
    __syncthreads();
    if (threadIdx.x < 64)
        atomicAdd(&g_opos[bh * NDH + d], part[0][d] + part[1][d] + part[2][d] + part[3][d]);
}

// =====================================================================
// Flash attention (fp32, unchanged from R5)
// =====================================================================
#define FLASH_SMEM_FLOATS (4 * 64 * 68 + 64)
#define FLASH_SMEM_BYTES  (FLASH_SMEM_FLOATS * 4)

__global__ void __launch_bounds__(256, 3)
attn_flash(const float* __restrict__ gate) {
    extern __shared__ float sm[];
    float (*Qs)[68] = (float(*)[68])(sm);
    float (*Ks)[68] = (float(*)[68])(sm + 4352);
    float (*Vs)[68] = (float(*)[68])(sm + 8704);
    float (*Ps)[68] = (float(*)[68])(sm + 13056);
    float* opos_s = sm + 17408;

    int tid = threadIdx.x;
    int bh = blockIdx.y;
    int q0 = blockIdx.x * 64;
    int h = bh & 7, b = bh >> 3;
    const float* Qg = g_q + (size_t)bh * NS * NDH;
    const float* Kg = g_k + (size_t)bh * NS * NDH;
    const float* Vg = g_v + (size_t)bh * NS * NDH;

    float gv = 1.0f / (1.0f + __expf(-gate[h]));
    float og = 1.0f - gv;

    int r4 = tid >> 2;
    int d0 = (tid & 3) * 16;
    #pragma unroll
    for (int c = 0; c < 4; c++) {
        float4 v = *(const float4*)&Qg[(q0 + r4) * NDH + d0 + c * 4];
        Qs[d0 + c * 4 + 0][r4] = v.x;
        Qs[d0 + c * 4 + 1][r4] = v.y;
        Qs[d0 + c * 4 + 2][r4] = v.z;
        Qs[d0 + c * 4 + 3][r4] = v.w;
    }
    if (tid < 64) opos_s[tid] = g_opos[bh * NDH + tid];
    __syncthreads();

    int tx = tid & 15, ty = tid >> 4;
    float o[4][4] = {};
    float mrow[4], lrow[4];
    #pragma unroll
    for (int i = 0; i < 4; i++) { mrow[i] = -1e30f; lrow[i] = 0.0f; }

    for (int kc = 0; kc < 8; kc++) {
        #pragma unroll
        for (int c = 0; c < 4; c++) {
            float4 v = *(const float4*)&Kg[(kc * 64 + r4) * NDH + d0 + c * 4];
            Ks[d0 + c * 4 + 0][r4] = v.x;
            Ks[d0 + c * 4 + 1][r4] = v.y;
            Ks[d0 + c * 4 + 2][r4] = v.z;
            Ks[d0 + c * 4 + 3][r4] = v.w;
            *(float4*)&Vs[r4][d0 + c * 4] =
                *(const float4*)&Vg[(kc * 64 + r4) * NDH + d0 + c * 4];
        }
        __syncthreads();

        float s[4][4] = {};
        #pragma unroll
        for (int d = 0; d < 64; d++) {
            float4 a  = *(float4*)&Qs[d][ty * 4];
            float4 bv = *(float4*)&Ks[d][tx * 4];
            float av[4] = {a.x, a.y, a.z, a.w};
            float bb[4] = {bv.x, bv.y, bv.z, bv.w};
            #pragma unroll
            for (int i = 0; i < 4; i++)
                #pragma unroll
                for (int j = 0; j < 4; j++)
                    s[i][j] += av[i] * bb[j];
        }

        #pragma unroll
        for (int i = 0; i < 4; i++) {
            float mx = fmaxf(fmaxf(s[i][0], s[i][1]), fmaxf(s[i][2], s[i][3])) * 0.125f;
            #pragma unroll
            for (int off = 1; off < 16; off <<= 1)
                mx = fmaxf(mx, __shfl_xor_sync(0xFFFFFFFF, mx, off));
            float mn = fmaxf(mrow[i], mx);
            float alpha = __expf(mrow[i] - mn);
            float rs = 0.0f;
            #pragma unroll
            for (int j = 0; j < 4; j++) {
                float p = __expf(s[i][j] * 0.125f - mn);
                s[i][j] = p;
                rs += p;
            }
            #pragma unroll
            for (int off = 1; off < 16; off <<= 1)
                rs += __shfl_xor_sync(0xFFFFFFFF, rs, off);
            lrow[i] = lrow[i] * alpha + rs;
            mrow[i] = mn;
            #pragma unroll
            for (int j = 0; j < 4; j++) o[i][j] *= alpha;
            *(float4*)&Ps[ty * 4 + i][tx * 4] = make_float4(s[i][0], s[i][1], s[i][2], s[i][3]);
        }
        __syncthreads();

        #pragma unroll
        for (int k4 = 0; k4 < 64; k4 += 4) {
            float4 ar[4];
            #pragma unroll
            for (int i = 0; i < 4; i++)
                ar[i] = *(float4*)&Ps[ty * 4 + i][k4];
            float a[4][4] = {{ar[0].x, ar[0].y, ar[0].z, ar[0].w},
                             {ar[1].x, ar[1].y, ar[1].z, ar[1].w},
                             {ar[2].x, ar[2].y, ar[2].z, ar[2].w},
                             {ar[3].x, ar[3].y, ar[3].z, ar[3].w}};
            #pragma unroll
            for (int kk = 0; kk < 4; kk++) {
                float4 bv = *(float4*)&Vs[k4 + kk][tx * 4];
                float bb[4] = {bv.x, bv.y, bv.z, bv.w};
                #pragma unroll
                for (int i = 0; i < 4; i++)
                    #pragma unroll
                    for (int j = 0; j < 4; j++)
                        o[i][j] += a[i][kk] * bb[j];
            }
        }
        __syncthreads();
    }

    #pragma unroll
    for (int i = 0; i < 4; i++) {
        int q = q0 + ty * 4 + i;
        float f = og / lrow[i];
        float4 v = make_float4(o[i][0] * f + gv * opos_s[tx * 4 + 0],
                               o[i][1] * f + gv * opos_s[tx * 4 + 1],
                               o[i][2] * f + gv * opos_s[tx * 4 + 2],
                               o[i][3] * f + gv * opos_s[tx * 4 + 3]);
        *(float4*)&g_y[((size_t)b * NS + q) * NDIM + h * NDH + tx * 4] = v;
    }
}

extern "C" void kernel_launch(void* const* d_in, const int* in_sizes, int n_in,
                              void* d_out, int out_size) {
    const float* x    = (const float*)d_in[0];
    const float* pos  = (const float*)d_in[1];
    const float* Wq   = (const float*)d_in[2];
    const float* Wk   = (const float*)d_in[3];
    const float* Wv   = (const float*)d_in[4];
    const float* Wo   = (const float*)d_in[5];
    const float* bo   = (const float*)d_in[6];
    const float* Wp1  = (const float*)d_in[7];
    const float* bp1  = (const float*)d_in[8];
    const float* Wp2  = (const float*)d_in[9];
    const float* bp2  = (const float*)d_in[10];
    const float* Wh   = (const float*)d_in[11];
    // d_in[12] = bh : cancels inside softmax (constant along k axis) — unused
    const float* gate = (const float*)d_in[13];
    float* out = (float*)d_out;

    static bool attr_set = false;
    if (!attr_set) {
        cudaFuncSetAttribute(attn_flash, cudaFuncAttributeMaxDynamicSharedMemorySize, FLASH_SMEM_BYTES);
        attr_set = true;
    }

    u_kernel<<<8, 256>>>(pos, Wp1, bp1, Wp2, bp2, Wh);
    pos_w_kernel<<<32, 512>>>();
    split_w_kernel<<<2048, 128>>>(Wq, Wk, Wv, Wo);
    split_x_kernel<<<2048, 128>>>(x);
    qkv_mma<<<dim3(4, 16, 3), 256>>>();
    opos_kernel<<<dim3(32, 4), 256>>>();
    attn_flash<<<dim3(8, 32), 256, FLASH_SMEM_BYTES>>>(gate);
    split_y_kernel<<<2048, 128>>>();
    out_mma<<<dim3(4, 16), 256>>>(bo, out);
}

// round 7
// speedup vs baseline: 1.4597x; 1.1282x over previous
#include <cuda_runtime.h>
#include <math.h>

#define NB 4
#define NS 512
#define NDIM 512
#define NH 8
#define NDH 64
#define NM (NB*NS)     // 2048

// ---------------- device scratch (no allocations allowed) ----------------
__device__ float g_q[NB*NH*NS*NDH];     // [b][h][s][d]
__device__ float g_k[NB*NH*NS*NDH];
__device__ float g_v[NB*NH*NS*NDH];
__device__ float g_u[NB*NS*NH];         // [b][s][h]
__device__ float g_w[NB*NH*NS];         // [b][h][k]
__device__ float g_opos[NB*NH*NDH];     // [b][h][d] : w @ V
__device__ float g_y[NM*NDIM];          // pre-output-projection activations

// tf32 hi/lo pre-split, pre-permuted into mma fragment order:
// A-side, [mblk(128)][kblk(64)][lane(32)][reg(4)]
__device__ float g_xh[NM*NDIM], g_xl[NM*NDIM];
__device__ float g_yh[NM*NDIM], g_yl[NM*NDIM];
// B-side, per matrix [kblk(64)][nblk(64)][lane(32)][reg(2)]; mat: 0=Wq 1=Wk 2=Wv 3=Wo
__device__ float g_wh[4*NDIM*NDIM], g_wl[4*NDIM*NDIM];

__device__ __forceinline__ unsigned f2tf(float x) {
    unsigned r;
    asm("cvt.rna.tf32.f32 %0, %1;" : "=r"(r) : "f"(x));
    return r;
}

__device__ __forceinline__ void mma_tf32(float (&d)[4], const unsigned (&a)[4],
                                         unsigned b0, unsigned b1) {
    asm volatile(
        "mma.sync.aligned.m16n8k8.row.col.f32.tf32.tf32.f32 "
        "{%0,%1,%2,%3}, {%4,%5,%6,%7}, {%8,%9}, {%0,%1,%2,%3};"
        : "+f"(d[0]), "+f"(d[1]), "+f"(d[2]), "+f"(d[3])
        : "r"(a[0]), "r"(a[1]), "r"(a[2]), "r"(a[3]), "r"(b0), "r"(b1));
}

__device__ __forceinline__ unsigned cvta_sh(const void* p) {
    return (unsigned)__cvta_generic_to_shared(p);
}
#define CPA16(dst, src) \
    asm volatile("cp.async.cg.shared.global [%0], [%1], 16;" :: "r"(dst), "l"(src))

// ---------------- coalesced split kernels ----------------
// A-side: warp owns one (mblk,kblk); lane writes one contiguous float4 (h & l).
__device__ __forceinline__ void split_a2(const float* __restrict__ src,
                                         float* __restrict__ dh, float* __restrict__ dl) {
    int gw = blockIdx.x * 8 + (threadIdx.x >> 5);    // 0..8191
    int lane = threadIdx.x & 31;
    int mblk = gw >> 6, kblk = gw & 63;
    float h[4], l[4];
    #pragma unroll
    for (int r = 0; r < 4; r++) {
        int mr = (lane >> 2) | ((r & 1) << 3);
        int kc = (lane & 3) | ((r >> 1) << 2);
        float v = src[(mblk * 16 + mr) * NDIM + kblk * 8 + kc];
        h[r] = __uint_as_float(f2tf(v));
        l[r] = __uint_as_float(f2tf(v - h[r]));
    }
    int idx = (gw * 32 + lane) * 4;
    *(float4*)&dh[idx] = make_float4(h[0], h[1], h[2], h[3]);
    *(float4*)&dl[idx] = make_float4(l[0], l[1], l[2], l[3]);
}
__global__ void split_x_kernel(const float* __restrict__ X) { split_a2(X, g_xh, g_xl); }
__global__ void split_y_kernel() { split_a2(g_y, g_yh, g_yl); }

// B-side: warp owns one (mat,kblk,nblk); lane writes contiguous float2 (h & l).
__global__ void split_w_kernel(const float* __restrict__ Wq, const float* __restrict__ Wk,
                               const float* __restrict__ Wv, const float* __restrict__ Wo) {
    int gw = blockIdx.x * 8 + (threadIdx.x >> 5);    // 0..16383
    int lane = threadIdx.x & 31;
    int mat = gw >> 12;
    int rem = gw & 4095;
    int kblk = rem >> 6, nblk = rem & 63;
    const float* W = (mat == 0) ? Wq : (mat == 1) ? Wk : (mat == 2) ? Wv : Wo;
    int nc = lane >> 2, tl = lane & 3;
    float h[2], l[2];
    #pragma unroll
    for (int r = 0; r < 2; r++) {
        int kc = tl | (r << 2);
        float v = W[(kblk * 8 + kc) * NDIM + nblk * 8 + nc];
        h[r] = __uint_as_float(f2tf(v));
        l[r] = __uint_as_float(f2tf(v - h[r]));
    }
    int idx = mat * NDIM * NDIM + (rem * 32 + lane) * 2;
    *(float2*)&g_wh[idx] = make_float2(h[0], h[1]);
    *(float2*)&g_wl[idx] = make_float2(l[0], l[1]);
}

// =====================================================================
// tf32 x3 MMA GEMM, 128x128 tile, 8 warps, cp.async double-buffered smem.
// smem floats: sAh[2][1024] sAl[2][1024] sBh[2][1024] sBl[2][1024] = 32KB
// =====================================================================
__device__ __forceinline__ void mma_gemm_tile2(const float* __restrict__ Ah,
                                               const float* __restrict__ Al,
                                               const float* __restrict__ Bh,
                                               const float* __restrict__ Bl,
                                               int mblk0, int nblk0,
                                               float (&acc)[2][8][4], float* sm) {
    float* sAh = sm;
    float* sAl = sm + 2048;
    float* sBh = sm + 4096;
    float* sBl = sm + 6144;
    int tid = threadIdx.x, lane = tid & 31, wid = tid >> 5;
    int warp_m = wid >> 1, warp_n = wid & 1;
    int a_mblk = tid >> 5, a_lane = tid & 31;          // A: 8 mblk x 32 lanes, 16B each
    int b_nblk = tid >> 4, b_pair = (tid & 15) * 2;    // B: 16 nblk x 16 pairs, 16B each

    unsigned dAh = cvta_sh(&sAh[a_mblk * 128 + a_lane * 4]);
    unsigned dAl = cvta_sh(&sAl[a_mblk * 128 + a_lane * 4]);
    unsigned dBh = cvta_sh(&sBh[b_nblk * 64 + b_pair * 2]);
    unsigned dBl = cvta_sh(&sBl[b_nblk * 64 + b_pair * 2]);
    const float* srcAh = &Ah[((mblk0 + a_mblk) * 64) * 128 + a_lane * 4];
    const float* srcAl = &Al[((mblk0 + a_mblk) * 64) * 128 + a_lane * 4];
    const float* srcBh = &Bh[(nblk0 + b_nblk) * 64 + b_pair * 2];
    const float* srcBl = &Bl[(nblk0 + b_nblk) * 64 + b_pair * 2];

    // issue stage kb into buffer buf
    auto issue = [&](int kb, int buf) {
        CPA16(dAh + buf * 4096, srcAh + kb * 128);
        CPA16(dAl + buf * 4096, srcAl + kb * 128);
        CPA16(dBh + buf * 4096, srcBh + (size_t)kb * 64 * 64);
        CPA16(dBl + buf * 4096, srcBl + (size_t)kb * 64 * 64);
        asm volatile("cp.async.commit_group;");
    };

    issue(0, 0);
    int buf = 0;
    for (int kb = 0; kb < 64; kb++) {
        if (kb < 63) {
            issue(kb + 1, buf ^ 1);
            asm volatile("cp.async.wait_group 1;");
        } else {
            asm volatile("cp.async.wait_group 0;");
        }
        __syncthreads();

        unsigned ah[2][4], al[2][4];
        #pragma unroll
        for (int mb2 = 0; mb2 < 2; mb2++) {
            float4 h4 = *(float4*)&sAh[buf * 1024 + (warp_m * 2 + mb2) * 128 + lane * 4];
            float4 l4 = *(float4*)&sAl[buf * 1024 + (warp_m * 2 + mb2) * 128 + lane * 4];
            ah[mb2][0] = __float_as_uint(h4.x); ah[mb2][1] = __float_as_uint(h4.y);
            ah[mb2][2] = __float_as_uint(h4.z); ah[mb2][3] = __float_as_uint(h4.w);
            al[mb2][0] = __float_as_uint(l4.x); al[mb2][1] = __float_as_uint(l4.y);
            al[mb2][2] = __float_as_uint(l4.z); al[mb2][3] = __float_as_uint(l4.w);
        }
        #pragma unroll
        for (int nb = 0; nb < 8; nb++) {
            float2 h2 = *(float2*)&sBh[buf * 1024 + (warp_n * 8 + nb) * 64 + lane * 2];
            float2 l2 = *(float2*)&sBl[buf * 1024 + (warp_n * 8 + nb) * 64 + lane * 2];
            unsigned b0h = __float_as_uint(h2.x), b1h = __float_as_uint(h2.y);
            unsigned b0l = __float_as_uint(l2.x), b1l = __float_as_uint(l2.y);
            #pragma unroll
            for (int mb2 = 0; mb2 < 2; mb2++) {
                mma_tf32(acc[mb2][nb], ah[mb2], b0h, b1h);
                mma_tf32(acc[mb2][nb], ah[mb2], b0l, b1l);
                mma_tf32(acc[mb2][nb], al[mb2], b0h, b1h);
            }
        }
        __syncthreads();
        buf ^= 1;
    }
}

// ---------------- QKV projection (tf32 mma), scatter to [b,h,s,d] --------
__global__ void __launch_bounds__(256, 2)
qkv_mma() {
    __shared__ float sm[8192];
    int mat = blockIdx.z;                    // 0=q 1=k 2=v
    float* out = (mat == 0) ? g_q : (mat == 1) ? g_k : g_v;
    const float* Bh = g_wh + mat * NDIM * NDIM;
    const float* Bl = g_wl + mat * NDIM * NDIM;
    int m0 = blockIdx.y * 128, n0 = blockIdx.x * 128;
    float acc[2][8][4] = {};
    mma_gemm_tile2(g_xh, g_xl, Bh, Bl, m0 >> 4, n0 >> 3, acc, sm);

    int lane = threadIdx.x & 31, wid = threadIdx.x >> 5;
    int warp_m = wid >> 1, warp_n = wid & 1;
    int g = lane >> 2, t = lane & 3;
    #pragma unroll
    for (int mb2 = 0; mb2 < 2; mb2++) {
        int mrow = m0 + warp_m * 32 + mb2 * 16 + g;
        #pragma unroll
        for (int nb = 0; nb < 8; nb++) {
            int ncol = n0 + (warp_n * 8 + nb) * 8 + 2 * t;
            int h = ncol >> 6, d = ncol & 63;
            {
                int b = mrow >> 9, s = mrow & 511;
                *(float2*)&out[((b * NH + h) * NS + s) * NDH + d] =
                    make_float2(acc[mb2][nb][0], acc[mb2][nb][1]);
            }
            {
                int m2 = mrow + 8;
                int b = m2 >> 9, s = m2 & 511;
                *(float2*)&out[((b * NH + h) * NS + s) * NDH + d] =
                    make_float2(acc[mb2][nb][2], acc[mb2][nb][3]);
            }
        }
    }
}

// ---------------- out = y @ Wo + bo (tf32 mma) ----------------
__global__ void __launch_bounds__(256, 2)
out_mma(const float* __restrict__ bo, float* __restrict__ out) {
    __shared__ float sm[8192];
    const float* Bh = g_wh + 3 * NDIM * NDIM;
    const float* Bl = g_wl + 3 * NDIM * NDIM;
    int m0 = blockIdx.y * 128, n0 = blockIdx.x * 128;
    float acc[2][8][4] = {};
    mma_gemm_tile2(g_yh, g_yl, Bh, Bl, m0 >> 4, n0 >> 3, acc, sm);

    int lane = threadIdx.x & 31, wid = threadIdx.x >> 5;
    int warp_m = wid >> 1, warp_n = wid & 1;
    int g = lane >> 2, t = lane & 3;
    #pragma unroll
    for (int mb2 = 0; mb2 < 2; mb2++) {
        int mrow = m0 + warp_m * 32 + mb2 * 16 + g;
        #pragma unroll
        for (int nb = 0; nb < 8; nb++) {
            int ncol = n0 + (warp_n * 8 + nb) * 8 + 2 * t;
            float b0 = bo[ncol], b1 = bo[ncol + 1];
            *(float2*)&out[(size_t)mrow * NDIM + ncol] =
                make_float2(acc[mb2][nb][0] + b0, acc[mb2][nb][1] + b1);
            *(float2*)&out[(size_t)(mrow + 8) * NDIM + ncol] =
                make_float2(acc[mb2][nb][2] + b0, acc[mb2][nb][3] + b1);
        }
    }
}

// ---------------- tiny positional MLP: u[b,s,h]; also zero g_opos --------
__global__ void u_kernel(const float* __restrict__ pos,
                         const float* __restrict__ Wp1, const float* __restrict__ bp1,
                         const float* __restrict__ Wp2, const float* __restrict__ bp2,
                         const float* __restrict__ Wh) {
    int idx = blockIdx.x * blockDim.x + threadIdx.x;
    if (idx >= NM) return;
    g_opos[idx & (NB*NH*NDH - 1)] = 0.0f;
    const float* pp = pos + idx * 3;
    float p0 = pp[0], p1 = pp[1], p2 = pp[2];
    float h1[3];
    #pragma unroll
    for (int j = 0; j < 3; j++)
        h1[j] = fmaxf(0.0f, p0 * Wp1[j] + p1 * Wp1[3 + j] + p2 * Wp1[6 + j] + bp1[j]);
    float u[NH];
    #pragma unroll
    for (int hh = 0; hh < NH; hh++) u[hh] = 0.0f;
    for (int j = 0; j < 64; j++) {
        float pv = h1[0] * Wp2[j] + h1[1] * Wp2[64 + j] + h1[2] * Wp2[128 + j] + bp2[j];
        #pragma unroll
        for (int hh = 0; hh < NH; hh++) u[hh] += pv * Wh[j * NH + hh];
    }
    #pragma unroll
    for (int hh = 0; hh < NH; hh++) g_u[idx * NH + hh] = u[hh];
}

// w[b,h,k] = softmax_k(-u[b,k,h])
__global__ void pos_w_kernel() {
    __shared__ float red[512];
    int bh = blockIdx.x;
    int b = bh >> 3, h = bh & 7;
    int k = threadIdx.x;
    float t = -g_u[(b * NS + k) * NH + h];
    red[k] = t; __syncthreads();
    for (int s = 256; s > 0; s >>= 1) { if (k < s) red[k] = fmaxf(red[k], red[k + s]); __syncthreads(); }
    float m = red[0]; __syncthreads();
    float e = expf(t - m);
    red[k] = e; __syncthreads();
    for (int s = 256; s > 0; s >>= 1) { if (k < s) red[k] += red[k + s]; __syncthreads(); }
    g_w[bh * NS + k] = e / red[0];
}

// O_pos[bh][d] += partial(w @ V) : split-K over 4 CTAs per bh
__global__ void opos_kernel() {
    __shared__ float part[4][64];
    int bh = blockIdx.x;
    int kq = blockIdx.y;
    int d = threadIdx.x & 63;
    int ks = threadIdx.x >> 6;
    const float* V = g_v + (size_t)bh * NS * NDH;
    const float* w = g_w + bh * NS;
    int kbase = kq * 128 + ks * 32;
    float s = 0.0f;
    #pragma unroll 4
    for (int k = kbase; k < kbase + 32; k++)
        s += w[k] * V[k * NDH + d];
    part[ks][d] = s;
    __syncthreads();
    if (threadIdx.x < 64)
        atomicAdd(&g_opos[bh * NDH + d], part[0][d] + part[1][d] + part[2][d] + part[3][d]);
}

// =====================================================================
// Flash attention (fp32, unchanged)
// =====================================================================
#define FLASH_SMEM_FLOATS (4 * 64 * 68 + 64)
#define FLASH_SMEM_BYTES  (FLASH_SMEM_FLOATS * 4)

__global__ void __launch_bounds__(256, 3)
attn_flash(const float* __restrict__ gate) {
    extern __shared__ float sm[];
    float (*Qs)[68] = (float(*)[68])(sm);
    float (*Ks)[68] = (float(*)[68])(sm + 4352);
    float (*Vs)[68] = (float(*)[68])(sm + 8704);
    float (*Ps)[68] = (float(*)[68])(sm + 13056);
    float* opos_s = sm + 17408;

    int tid = threadIdx.x;
    int bh = blockIdx.y;
    int q0 = blockIdx.x * 64;
    int h = bh & 7, b = bh >> 3;
    const float* Qg = g_q + (size_t)bh * NS * NDH;
    const float* Kg = g_k + (size_t)bh * NS * NDH;
    const float* Vg = g_v + (size_t)bh * NS * NDH;

    float gv = 1.0f / (1.0f + __expf(-gate[h]));
    float og = 1.0f - gv;

    int r4 = tid >> 2;
    int d0 = (tid & 3) * 16;
    #pragma unroll
    for (int c = 0; c < 4; c++) {
        float4 v = *(const float4*)&Qg[(q0 + r4) * NDH + d0 + c * 4];
        Qs[d0 + c * 4 + 0][r4] = v.x;
        Qs[d0 + c * 4 + 1][r4] = v.y;
        Qs[d0 + c * 4 + 2][r4] = v.z;
        Qs[d0 + c * 4 + 3][r4] = v.w;
    }
    if (tid < 64) opos_s[tid] = g_opos[bh * NDH + tid];
    __syncthreads();

    int tx = tid & 15, ty = tid >> 4;
    float o[4][4] = {};
    float mrow[4], lrow[4];
    #pragma unroll
    for (int i = 0; i < 4; i++) { mrow[i] = -1e30f; lrow[i] = 0.0f; }

    for (int kc = 0; kc < 8; kc++) {
        #pragma unroll
        for (int c = 0; c < 4; c++) {
            float4 v = *(const float4*)&Kg[(kc * 64 + r4) * NDH + d0 + c * 4];
            Ks[d0 + c * 4 + 0][r4] = v.x;
            Ks[d0 + c * 4 + 1][r4] = v.y;
            Ks[d0 + c * 4 + 2][r4] = v.z;
            Ks[d0 + c * 4 + 3][r4] = v.w;
            *(float4*)&Vs[r4][d0 + c * 4] =
                *(const float4*)&Vg[(kc * 64 + r4) * NDH + d0 + c * 4];
        }
        __syncthreads();

        float s[4][4] = {};
        #pragma unroll
        for (int d = 0; d < 64; d++) {
            float4 a  = *(float4*)&Qs[d][ty * 4];
            float4 bv = *(float4*)&Ks[d][tx * 4];
            float av[4] = {a.x, a.y, a.z, a.w};
            float bb[4] = {bv.x, bv.y, bv.z, bv.w};
            #pragma unroll
            for (int i = 0; i < 4; i++)
                #pragma unroll
                for (int j = 0; j < 4; j++)
                    s[i][j] += av[i] * bb[j];
        }

        #pragma unroll
        for (int i = 0; i < 4; i++) {
            float mx = fmaxf(fmaxf(s[i][0], s[i][1]), fmaxf(s[i][2], s[i][3])) * 0.125f;
            #pragma unroll
            for (int off = 1; off < 16; off <<= 1)
                mx = fmaxf(mx, __shfl_xor_sync(0xFFFFFFFF, mx, off));
            float mn = fmaxf(mrow[i], mx);
            float alpha = __expf(mrow[i] - mn);
            float rs = 0.0f;
            #pragma unroll
            for (int j = 0; j < 4; j++) {
                float p = __expf(s[i][j] * 0.125f - mn);
                s[i][j] = p;
                rs += p;
            }
            #pragma unroll
            for (int off = 1; off < 16; off <<= 1)
                rs += __shfl_xor_sync(0xFFFFFFFF, rs, off);
            lrow[i] = lrow[i] * alpha + rs;
            mrow[i] = mn;
            #pragma unroll
            for (int j = 0; j < 4; j++) o[i][j] *= alpha;
            *(float4*)&Ps[ty * 4 + i][tx * 4] = make_float4(s[i][0], s[i][1], s[i][2], s[i][3]);
        }
        __syncthreads();

        #pragma unroll
        for (int k4 = 0; k4 < 64; k4 += 4) {
            float4 ar[4];
            #pragma unroll
            for (int i = 0; i < 4; i++)
                ar[i] = *(float4*)&Ps[ty * 4 + i][k4];
            float a[4][4] = {{ar[0].x, ar[0].y, ar[0].z, ar[0].w},
                             {ar[1].x, ar[1].y, ar[1].z, ar[1].w},
                             {ar[2].x, ar[2].y, ar[2].z, ar[2].w},
                             {ar[3].x, ar[3].y, ar[3].z, ar[3].w}};
            #pragma unroll
            for (int kk = 0; kk < 4; kk++) {
                float4 bv = *(float4*)&Vs[k4 + kk][tx * 4];
                float bb[4] = {bv.x, bv.y, bv.z, bv.w};
                #pragma unroll
                for (int i = 0; i < 4; i++)
                    #pragma unroll
                    for (int j = 0; j < 4; j++)
                        o[i][j] += a[i][kk] * bb[j];
            }
        }
        __syncthreads();
    }

    #pragma unroll
    for (int i = 0; i < 4; i++) {
        int q = q0 + ty * 4 + i;
        float f = og / lrow[i];
        float4 v = make_float4(o[i][0] * f + gv * opos_s[tx * 4 + 0],
                               o[i][1] * f + gv * opos_s[tx * 4 + 1],
                               o[i][2] * f + gv * opos_s[tx * 4 + 2],
                               o[i][3] * f + gv * opos_s[tx * 4 + 3]);
        *(float4*)&g_y[((size_t)b * NS + q) * NDIM + h * NDH + tx * 4] = v;
    }
}

extern "C" void kernel_launch(void* const* d_in, const int* in_sizes, int n_in,
                              void* d_out, int out_size) {
    const float* x    = (const float*)d_in[0];
    const float* pos  = (const float*)d_in[1];
    const float* Wq   = (const float*)d_in[2];
    const float* Wk   = (const float*)d_in[3];
    const float* Wv   = (const float*)d_in[4];
    const float* Wo   = (const float*)d_in[5];
    const float* bo   = (const float*)d_in[6];
    const float* Wp1  = (const float*)d_in[7];
    const float* bp1  = (const float*)d_in[8];
    const float* Wp2  = (const float*)d_in[9];
    const float* bp2  = (const float*)d_in[10];
    const float* Wh   = (const float*)d_in[11];
    // d_in[12] = bh : cancels inside softmax (constant along k axis) — unused
    const float* gate = (const float*)d_in[13];
    float* out = (float*)d_out;

    static bool attr_set = false;
    if (!attr_set) {
        cudaFuncSetAttribute(attn_flash, cudaFuncAttributeMaxDynamicSharedMemorySize, FLASH_SMEM_BYTES);
        attr_set = true;
    }

    u_kernel<<<8, 256>>>(pos, Wp1, bp1, Wp2, bp2, Wh);
    pos_w_kernel<<<32, 512>>>();
    split_w_kernel<<<2048, 256>>>(Wq, Wk, Wv, Wo);
    split_x_kernel<<<1024, 256>>>(x);
    qkv_mma<<<dim3(4, 16, 3), 256>>>();
    opos_kernel<<<dim3(32, 4), 256>>>();
    attn_flash<<<dim3(8, 32), 256, FLASH_SMEM_BYTES>>>(gate);
    split_y_kernel<<<1024, 256>>>();
    out_mma<<<dim3(4, 16), 256>>>(bo, out);
}